// round 6
// baseline (speedup 1.0000x reference)
#include <cuda_runtime.h>
#include <cuda_bf16.h>
#include <stdint.h>
#include <math.h>

// Problem constants
#define BB 2
#define TT 2048
#define DM 2048
#define HH 16
#define DK 128
#define DV 128
#define KW 4
#define CDIM 6144          // 2*H*DK + H*DV
#define MTOK 4096          // B*T

// ---------------- scratch (device globals; no allocation allowed) ----------------
__device__ float g_mixed[(size_t)MTOK * CDIM];
__device__ float g_y[(size_t)MTOK * CDIM];
__device__ float g_qn[(size_t)MTOK * 2048];
__device__ float g_kn[(size_t)MTOK * 2048];
__device__ float g_beta[(size_t)MTOK * HH];
__device__ float g_decay[(size_t)MTOK * HH];
__device__ float g_o[(size_t)MTOK * 2048];
__device__ float g_z[(size_t)MTOK * 2048];
__device__ float g_on[(size_t)MTOK * 2048];

// ---------------- 3xTF32 tensor-core GEMM: C[m,n] = sum_k A[m*K+k]*W[n*K+k] ----
// 128x128 tile, BK=16, 256 threads (8 warps, warp tile 32x64), cp.async double buf.
// Split precision: x = hi + lo; acc += ah*bh + ah*bl + al*bh  (error ~2^-23).
#define PADA 20   // smem row stride in floats

__device__ __forceinline__ unsigned int f2tf(float x) {
    unsigned int r;
    asm("cvt.rna.tf32.f32 %0, %1;" : "=r"(r) : "f"(x));
    return r;
}

__device__ __forceinline__ void split_tf(float x, unsigned int& hi, unsigned int& lo) {
    hi = f2tf(x);
    lo = f2tf(x - __uint_as_float(hi));
}

__device__ __forceinline__ void cp16(unsigned int dst, const float* src) {
    asm volatile("cp.async.cg.shared.global [%0], [%1], 16;" ::"r"(dst), "l"(src));
}

__device__ __forceinline__ void mma8(float* c, const unsigned int* a, const unsigned int* b) {
    asm volatile(
        "mma.sync.aligned.m16n8k8.row.col.f32.tf32.tf32.f32 "
        "{%0,%1,%2,%3}, {%4,%5,%6,%7}, {%8,%9}, {%0,%1,%2,%3};"
        : "+f"(c[0]), "+f"(c[1]), "+f"(c[2]), "+f"(c[3])
        : "r"(a[0]), "r"(a[1]), "r"(a[2]), "r"(a[3]), "r"(b[0]), "r"(b[1]));
}

__global__ __launch_bounds__(256) void gemm_tf32(const float* __restrict__ A,
                                                 const float* __restrict__ W,
                                                 float* __restrict__ C,
                                                 int M, int N, int K) {
    __shared__ __align__(16) float As[2][128][PADA];
    __shared__ __align__(16) float Bs[2][128][PADA];

    const int tid = threadIdx.x;
    const int bm = blockIdx.y * 128, bn = blockIdx.x * 128;
    const int warp = tid >> 5, lane = tid & 31;
    const int wm = (warp & 3) * 32;      // warp m offset (4 warps in m)
    const int wn = (warp >> 2) * 64;     // warp n offset (2 warps in n)
    const int g = lane >> 2, tg = lane & 3;

    // staging: each thread loads two 16B chunks per matrix per tile
    const int row = tid >> 1;
    const int c0 = (tid & 1) * 8;
    const float* Aptr = A + (size_t)(bm + row) * K + c0;
    const float* Wptr = W + (size_t)(bn + row) * K + c0;
    const unsigned int sa = (unsigned int)__cvta_generic_to_shared(&As[0][row][c0]);
    const unsigned int sb = (unsigned int)__cvta_generic_to_shared(&Bs[0][row][c0]);
    const unsigned int bufstride = (unsigned int)(128 * PADA * sizeof(float));

    float acc[2][8][4];
#pragma unroll
    for (int mi = 0; mi < 2; mi++)
#pragma unroll
        for (int ni = 0; ni < 8; ni++)
#pragma unroll
            for (int r = 0; r < 4; r++) acc[mi][ni][r] = 0.f;

    // stage buffer 0
    cp16(sa, Aptr);
    cp16(sa + 16, Aptr + 4);
    cp16(sb, Wptr);
    cp16(sb + 16, Wptr + 4);
    asm volatile("cp.async.commit_group;");

    for (int k0 = 0; k0 < K; k0 += 16) {
        const int buf = (k0 >> 4) & 1;
        if (k0 + 16 < K) {
            const unsigned int da = sa + (buf ^ 1) * bufstride;
            const unsigned int db = sb + (buf ^ 1) * bufstride;
            cp16(da, Aptr + k0 + 16);
            cp16(da + 16, Aptr + k0 + 20);
            cp16(db, Wptr + k0 + 16);
            cp16(db + 16, Wptr + k0 + 20);
            asm volatile("cp.async.commit_group;");
            asm volatile("cp.async.wait_group 1;");
        } else {
            asm volatile("cp.async.wait_group 0;");
        }
        __syncthreads();

#pragma unroll
        for (int kk = 0; kk < 16; kk += 8) {
            unsigned int ah[2][4], al[2][4];
            unsigned int bh[8][2], bl[8][2];
#pragma unroll
            for (int mi = 0; mi < 2; mi++) {
                const int m = wm + mi * 16;
                split_tf(As[buf][m + g][kk + tg], ah[mi][0], al[mi][0]);
                split_tf(As[buf][m + g + 8][kk + tg], ah[mi][1], al[mi][1]);
                split_tf(As[buf][m + g][kk + tg + 4], ah[mi][2], al[mi][2]);
                split_tf(As[buf][m + g + 8][kk + tg + 4], ah[mi][3], al[mi][3]);
            }
#pragma unroll
            for (int ni = 0; ni < 8; ni++) {
                const int n = wn + ni * 8;
                split_tf(Bs[buf][n + g][kk + tg], bh[ni][0], bl[ni][0]);
                split_tf(Bs[buf][n + g][kk + tg + 4], bh[ni][1], bl[ni][1]);
            }
#pragma unroll
            for (int mi = 0; mi < 2; mi++)
#pragma unroll
                for (int ni = 0; ni < 8; ni++) {
                    mma8(acc[mi][ni], al[mi], bh[ni]);
                    mma8(acc[mi][ni], ah[mi], bl[ni]);
                    mma8(acc[mi][ni], ah[mi], bh[ni]);
                }
        }
        __syncthreads();
    }

    // epilogue: c0,c1 at (row g, col tg*2), c2,c3 at (row g+8, col tg*2)
#pragma unroll
    for (int mi = 0; mi < 2; mi++) {
#pragma unroll
        for (int ni = 0; ni < 8; ni++) {
            const int r0 = bm + wm + mi * 16 + g;
            const int cc = bn + wn + ni * 8 + tg * 2;
            *(float2*)(C + (size_t)r0 * N + cc) =
                make_float2(acc[mi][ni][0], acc[mi][ni][1]);
            *(float2*)(C + (size_t)(r0 + 8) * N + cc) =
                make_float2(acc[mi][ni][2], acc[mi][ni][3]);
        }
    }
}

// ---------------- gates: beta = sigmoid(x.w_b), decay = exp(-exp(A_log)*softplus(x.w_a+dt_bias)) ----
__global__ __launch_bounds__(256) void proj_gates(const float* __restrict__ x,
                                                  const float* __restrict__ w_b,
                                                  const float* __restrict__ w_a,
                                                  const float* __restrict__ dt_bias,
                                                  const float* __restrict__ A_log) {
    const int m = blockIdx.x;
    __shared__ float xs[DM];
    for (int i = threadIdx.x; i < DM; i += 256) xs[i] = x[(size_t)m * DM + i];
    __syncthreads();
    const int warp = threadIdx.x >> 5, lane = threadIdx.x & 31;
    for (int d = warp; d < 32; d += 8) {
        const float* w = (d < HH) ? (w_b + (size_t)d * DM) : (w_a + (size_t)(d - HH) * DM);
        float s = 0.f;
        for (int i = lane; i < DM; i += 32) s += xs[i] * w[i];
#pragma unroll
        for (int off = 16; off; off >>= 1) s += __shfl_xor_sync(0xffffffffu, s, off);
        if (lane == 0) {
            if (d < HH) {
                g_beta[(size_t)m * HH + d] = 1.f / (1.f + expf(-s));
            } else {
                int h = d - HH;
                float sp = s + dt_bias[h];
                sp = (sp > 20.f) ? sp : log1pf(expf(sp));
                g_decay[(size_t)m * HH + h] = expf(-expf(A_log[h]) * sp);
            }
        }
    }
}

// ---------------- causal depthwise conv (KW=4) + SiLU ----------------
__global__ __launch_bounds__(256) void conv_silu(const float* __restrict__ conv_w) {
    const int c = blockIdx.x * 256 + threadIdx.x;
    const int bt = blockIdx.y;
    const int t = bt & (TT - 1);
    const float* base = g_mixed + (size_t)bt * CDIM + c;
    float4 w = *(const float4*)(conv_w + (size_t)c * KW);
    float acc = w.w * base[0];
    if (t >= 1) acc += w.z * base[-(ptrdiff_t)CDIM];
    if (t >= 2) acc += w.y * base[-(ptrdiff_t)(2 * CDIM)];
    if (t >= 3) acc += w.x * base[-(ptrdiff_t)(3 * CDIM)];
    float s = acc / (1.f + expf(-acc));
    g_y[(size_t)bt * CDIM + c] = s;
}

// ---------------- per-head L2 norm of q and k ----------------
__global__ __launch_bounds__(128) void qk_norm() {
    const int bt = blockIdx.x;
    const int hh = blockIdx.y;  // 0..15 q, 16..31 k
    const int off = (hh < HH) ? hh * DK : (HH * DK + (hh - HH) * DK);
    const float* src = g_y + (size_t)bt * CDIM + off;
    float u = src[threadIdx.x];
    float s = u * u;
#pragma unroll
    for (int o = 16; o; o >>= 1) s += __shfl_xor_sync(0xffffffffu, s, o);
    __shared__ float red[4];
    if ((threadIdx.x & 31) == 0) red[threadIdx.x >> 5] = s;
    __syncthreads();
    float tot = red[0] + red[1] + red[2] + red[3];
    float r = rsqrtf(tot + 1e-6f);
    float* dst = (hh < HH) ? g_qn : g_kn;
    dst[(size_t)bt * 2048 + (hh & 15) * DK + threadIdx.x] = u * r;
}

// ---------------- sequential delta-rule scan ----------------
__global__ __launch_bounds__(128) void scan_kernel(float* __restrict__ o) {
    const int bh = blockIdx.x;
    const int b = bh >> 4, h = bh & 15;
    const int jc = blockIdx.y;
    const int tid = threadIdx.x;
    const int jloc = tid >> 2;
    const int kg = tid & 3;

    __shared__ float ks[2][132], qs[2][132], vs[2][32], sc[2][2];
    float S[32];
#pragma unroll
    for (int i = 0; i < 32; i++) S[i] = 0.f;

    const int skew = (tid >> 5) * 33 + (tid & 31);

    const size_t qkbase = ((size_t)b * TT) * 2048 + h * DK;
    const size_t vbase = ((size_t)b * TT) * CDIM + 2 * HH * DK + h * DV + jc * 32;
    const size_t gbase = ((size_t)b * TT) * HH + h;
    const size_t obase = ((size_t)b * TT) * 2048 + h * DV + jc * 32 + jloc;

    float rk = g_kn[qkbase + tid];
    float rq = g_qn[qkbase + tid];
    float rv = (tid < 32) ? g_y[vbase + tid] : 0.f;
    float rb = g_beta[gbase], rd = g_decay[gbase];
    ks[0][skew] = rk;
    qs[0][skew] = rq;
    if (tid < 32) vs[0][tid] = rv;
    if (tid == 0) { sc[0][0] = rb; sc[0][1] = rd; }
    __syncthreads();

    for (int t = 0; t < TT; t++) {
        const int cur = t & 1;
        if (t + 1 < TT) {
            const size_t to = (size_t)(t + 1);
            rk = g_kn[qkbase + to * 2048 + tid];
            rq = g_qn[qkbase + to * 2048 + tid];
            if (tid < 32) rv = g_y[vbase + to * CDIM + tid];
            rb = g_beta[gbase + to * HH];
            rd = g_decay[gbase + to * HH];
        }
        const float bet = sc[cur][0];
        const float dec = sc[cur][1];
        const float vv = vs[cur][jloc];

        float kreg[32];
        float kv = 0.f;
#pragma unroll
        for (int i = 0; i < 32; i++) {
            kreg[i] = ks[cur][kg * 33 + i];
            S[i] *= dec;
            kv += kreg[i] * S[i];
        }
        kv += __shfl_xor_sync(0xffffffffu, kv, 1);
        kv += __shfl_xor_sync(0xffffffffu, kv, 2);
        const float delta = (vv - kv) * bet;

        float oacc = 0.f;
#pragma unroll
        for (int i = 0; i < 32; i++) {
            S[i] += kreg[i] * delta;
            oacc += qs[cur][kg * 33 + i] * S[i];
        }
        oacc += __shfl_xor_sync(0xffffffffu, oacc, 1);
        oacc += __shfl_xor_sync(0xffffffffu, oacc, 2);
        if (kg == 0) o[obase + (size_t)t * 2048] = oacc;

        if (t + 1 < TT) {
            const int nxt = cur ^ 1;
            ks[nxt][skew] = rk;
            qs[nxt][skew] = rq;
            if (tid < 32) vs[nxt][tid] = rv;
            if (tid == 0) { sc[nxt][0] = rb; sc[nxt][1] = rd; }
        }
        __syncthreads();
    }
}

// ---------------- gated RMSNorm per head ----------------
__global__ __launch_bounds__(128) void gated_norm(const float* __restrict__ norm_w) {
    const int g = blockIdx.x;  // bt*16 + h
    float u = g_o[(size_t)g * DV + threadIdx.x];
    float s = u * u;
#pragma unroll
    for (int o = 16; o; o >>= 1) s += __shfl_xor_sync(0xffffffffu, s, o);
    __shared__ float red[4];
    if ((threadIdx.x & 31) == 0) red[threadIdx.x >> 5] = s;
    __syncthreads();
    float tot = red[0] + red[1] + red[2] + red[3];
    float r = rsqrtf(tot * (1.f / DV) + 1e-6f);
    float zz = g_z[(size_t)g * DV + threadIdx.x];
    float sil = zz / (1.f + expf(-zz));
    g_on[(size_t)g * DV + threadIdx.x] = u * r * norm_w[threadIdx.x] * sil;
}

// ---------------- launch ----------------
extern "C" void kernel_launch(void* const* d_in, const int* in_sizes, int n_in,
                              void* d_out, int out_size) {
    const float* x = (const float*)d_in[0];
    const float* w_qkv = (const float*)d_in[1];
    const float* conv_w = (const float*)d_in[2];
    const float* w_z = (const float*)d_in[3];
    const float* w_b = (const float*)d_in[4];
    const float* w_a = (const float*)d_in[5];
    const float* dt_bias = (const float*)d_in[6];
    const float* A_log = (const float*)d_in[7];
    const float* norm_w = (const float*)d_in[8];
    const float* w_out = (const float*)d_in[9];
    float* out = (float*)d_out;

    float* mixed; cudaGetSymbolAddress((void**)&mixed, g_mixed);
    float* z;     cudaGetSymbolAddress((void**)&z, g_z);
    float* o;     cudaGetSymbolAddress((void**)&o, g_o);
    float* on;    cudaGetSymbolAddress((void**)&on, g_on);

    // 1. mixed = x @ w_qkv^T   [4096 x 6144]
    gemm_tf32<<<dim3(CDIM / 128, MTOK / 128), 256>>>(x, w_qkv, mixed, MTOK, CDIM, DM);
    // 2. gates
    proj_gates<<<MTOK, 256>>>(x, w_b, w_a, dt_bias, A_log);
    // 3. conv + silu
    conv_silu<<<dim3(CDIM / 256, MTOK), 256>>>(conv_w);
    // 4. q/k l2 norm
    qk_norm<<<dim3(MTOK, 2 * HH), 128>>>();
    // 5. z = x @ w_z^T  [4096 x 2048]
    gemm_tf32<<<dim3(2048 / 128, MTOK / 128), 256>>>(x, w_z, z, MTOK, 2048, DM);
    // 6. scan
    scan_kernel<<<dim3(BB * HH, 4), 128>>>(o);
    // 7. gated rmsnorm
    gated_norm<<<MTOK * HH, 128>>>(norm_w);
    // 8. out = on @ w_out^T  [4096 x 2048]
    gemm_tf32<<<dim3(2048 / 128, MTOK / 128), 256>>>(on, w_out, out, MTOK, 2048, DM);
}

// round 7
// speedup vs baseline: 1.4604x; 1.4604x over previous
#include <cuda_runtime.h>
#include <cuda_bf16.h>
#include <stdint.h>
#include <math.h>

// Problem constants
#define BB 2
#define TT 2048
#define DM 2048
#define HH 16
#define DK 128
#define DV 128
#define KW 4
#define CDIM 6144          // 2*H*DK + H*DV
#define MTOK 4096          // B*T

// ---------------- scratch (device globals; no allocation allowed) ----------------
__device__ float g_mixed[(size_t)MTOK * CDIM];
__device__ float g_y[(size_t)MTOK * CDIM];
__device__ float g_qn[(size_t)MTOK * 2048];
__device__ float g_kn[(size_t)MTOK * 2048];
__device__ float g_beta[(size_t)MTOK * HH];
__device__ float g_decay[(size_t)MTOK * HH];
__device__ float g_o[(size_t)MTOK * 2048];
__device__ float g_z[(size_t)MTOK * 2048];
__device__ float g_on[(size_t)MTOK * 2048];

// ---------------- 3xTF32 tensor-core GEMM: C[m,n] = sum_k A[m*K+k]*W[n*K+k] ----
// 128x128 tile, BK=16, 256 threads (8 warps, warp tile 32x64), cp.async double buf.
// Split precision: x = hi + lo; acc += ah*bh + ah*bl + al*bh  (error ~2^-22/product).
// Register-lean restructure: B split per n-tile inside the loop (4 live regs),
// launch_bounds(256,2) to force no spills + 2 blocks/SM.
#define PADA 20   // smem row stride in floats

__device__ __forceinline__ unsigned int f2tf(float x) {
    unsigned int r;
    asm("cvt.rna.tf32.f32 %0, %1;" : "=r"(r) : "f"(x));
    return r;
}

__device__ __forceinline__ void split_tf(float x, unsigned int& hi, unsigned int& lo) {
    hi = f2tf(x);
    lo = f2tf(x - __uint_as_float(hi));
}

__device__ __forceinline__ void cp16(unsigned int dst, const float* src) {
    asm volatile("cp.async.cg.shared.global [%0], [%1], 16;" ::"r"(dst), "l"(src));
}

__device__ __forceinline__ void mma8(float* c, const unsigned int* a, const unsigned int* b) {
    asm volatile(
        "mma.sync.aligned.m16n8k8.row.col.f32.tf32.tf32.f32 "
        "{%0,%1,%2,%3}, {%4,%5,%6,%7}, {%8,%9}, {%0,%1,%2,%3};"
        : "+f"(c[0]), "+f"(c[1]), "+f"(c[2]), "+f"(c[3])
        : "r"(a[0]), "r"(a[1]), "r"(a[2]), "r"(a[3]), "r"(b[0]), "r"(b[1]));
}

__global__ __launch_bounds__(256, 2) void gemm_tf32(const float* __restrict__ A,
                                                    const float* __restrict__ W,
                                                    float* __restrict__ C,
                                                    int M, int N, int K) {
    __shared__ __align__(16) float As[2][128][PADA];
    __shared__ __align__(16) float Bs[2][128][PADA];

    const int tid = threadIdx.x;
    const int bm = blockIdx.y * 128, bn = blockIdx.x * 128;
    const int warp = tid >> 5, lane = tid & 31;
    const int wm = (warp & 3) * 32;      // warp m offset (4 warps in m)
    const int wn = (warp >> 2) * 64;     // warp n offset (2 warps in n)
    const int g = lane >> 2, tg = lane & 3;

    // staging: each thread loads two 16B chunks per matrix per tile
    const int row = tid >> 1;
    const int c0 = (tid & 1) * 8;
    const float* Aptr = A + (size_t)(bm + row) * K + c0;
    const float* Wptr = W + (size_t)(bn + row) * K + c0;
    const unsigned int sa = (unsigned int)__cvta_generic_to_shared(&As[0][row][c0]);
    const unsigned int sb = (unsigned int)__cvta_generic_to_shared(&Bs[0][row][c0]);
    const unsigned int bufstride = (unsigned int)(128 * PADA * sizeof(float));

    float acc[2][8][4];
#pragma unroll
    for (int mi = 0; mi < 2; mi++)
#pragma unroll
        for (int ni = 0; ni < 8; ni++)
#pragma unroll
            for (int r = 0; r < 4; r++) acc[mi][ni][r] = 0.f;

    // stage buffer 0
    cp16(sa, Aptr);
    cp16(sa + 16, Aptr + 4);
    cp16(sb, Wptr);
    cp16(sb + 16, Wptr + 4);
    asm volatile("cp.async.commit_group;");

    for (int k0 = 0; k0 < K; k0 += 16) {
        const int buf = (k0 >> 4) & 1;
        if (k0 + 16 < K) {
            const unsigned int da = sa + (buf ^ 1) * bufstride;
            const unsigned int db = sb + (buf ^ 1) * bufstride;
            cp16(da, Aptr + k0 + 16);
            cp16(da + 16, Aptr + k0 + 20);
            cp16(db, Wptr + k0 + 16);
            cp16(db + 16, Wptr + k0 + 20);
            asm volatile("cp.async.commit_group;");
            asm volatile("cp.async.wait_group 1;");
        } else {
            asm volatile("cp.async.wait_group 0;");
        }
        __syncthreads();

#pragma unroll
        for (int kk = 0; kk < 16; kk += 8) {
            // A fragments: split once per kk (16 live regs)
            unsigned int ah[2][4], al[2][4];
#pragma unroll
            for (int mi = 0; mi < 2; mi++) {
                const int m = wm + mi * 16;
                split_tf(As[buf][m + g][kk + tg], ah[mi][0], al[mi][0]);
                split_tf(As[buf][m + g + 8][kk + tg], ah[mi][1], al[mi][1]);
                split_tf(As[buf][m + g][kk + tg + 4], ah[mi][2], al[mi][2]);
                split_tf(As[buf][m + g + 8][kk + tg + 4], ah[mi][3], al[mi][3]);
            }
            // B fragments: split per n-tile, only 4 live regs at a time
#pragma unroll
            for (int ni = 0; ni < 8; ni++) {
                const int n = wn + ni * 8;
                unsigned int bh[2], bl[2];
                split_tf(Bs[buf][n + g][kk + tg], bh[0], bl[0]);
                split_tf(Bs[buf][n + g][kk + tg + 4], bh[1], bl[1]);
#pragma unroll
                for (int mi = 0; mi < 2; mi++) {
                    mma8(acc[mi][ni], al[mi], bh);
                    mma8(acc[mi][ni], ah[mi], bl);
                    mma8(acc[mi][ni], ah[mi], bh);
                }
            }
        }
        __syncthreads();
    }

    // epilogue: c0,c1 at (row g, col tg*2), c2,c3 at (row g+8, col tg*2)
#pragma unroll
    for (int mi = 0; mi < 2; mi++) {
#pragma unroll
        for (int ni = 0; ni < 8; ni++) {
            const int r0 = bm + wm + mi * 16 + g;
            const int cc = bn + wn + ni * 8 + tg * 2;
            *(float2*)(C + (size_t)r0 * N + cc) =
                make_float2(acc[mi][ni][0], acc[mi][ni][1]);
            *(float2*)(C + (size_t)(r0 + 8) * N + cc) =
                make_float2(acc[mi][ni][2], acc[mi][ni][3]);
        }
    }
}

// ---------------- gates: beta = sigmoid(x.w_b), decay = exp(-exp(A_log)*softplus(x.w_a+dt_bias)) ----
__global__ __launch_bounds__(256) void proj_gates(const float* __restrict__ x,
                                                  const float* __restrict__ w_b,
                                                  const float* __restrict__ w_a,
                                                  const float* __restrict__ dt_bias,
                                                  const float* __restrict__ A_log) {
    const int m = blockIdx.x;
    __shared__ float xs[DM];
    for (int i = threadIdx.x; i < DM; i += 256) xs[i] = x[(size_t)m * DM + i];
    __syncthreads();
    const int warp = threadIdx.x >> 5, lane = threadIdx.x & 31;
    for (int d = warp; d < 32; d += 8) {
        const float* w = (d < HH) ? (w_b + (size_t)d * DM) : (w_a + (size_t)(d - HH) * DM);
        float s = 0.f;
        for (int i = lane; i < DM; i += 32) s += xs[i] * w[i];
#pragma unroll
        for (int off = 16; off; off >>= 1) s += __shfl_xor_sync(0xffffffffu, s, off);
        if (lane == 0) {
            if (d < HH) {
                g_beta[(size_t)m * HH + d] = 1.f / (1.f + expf(-s));
            } else {
                int h = d - HH;
                float sp = s + dt_bias[h];
                sp = (sp > 20.f) ? sp : log1pf(expf(sp));
                g_decay[(size_t)m * HH + h] = expf(-expf(A_log[h]) * sp);
            }
        }
    }
}

// ---------------- causal depthwise conv (KW=4) + SiLU ----------------
__global__ __launch_bounds__(256) void conv_silu(const float* __restrict__ conv_w) {
    const int c = blockIdx.x * 256 + threadIdx.x;
    const int bt = blockIdx.y;
    const int t = bt & (TT - 1);
    const float* base = g_mixed + (size_t)bt * CDIM + c;
    float4 w = *(const float4*)(conv_w + (size_t)c * KW);
    float acc = w.w * base[0];
    if (t >= 1) acc += w.z * base[-(ptrdiff_t)CDIM];
    if (t >= 2) acc += w.y * base[-(ptrdiff_t)(2 * CDIM)];
    if (t >= 3) acc += w.x * base[-(ptrdiff_t)(3 * CDIM)];
    float s = acc / (1.f + expf(-acc));
    g_y[(size_t)bt * CDIM + c] = s;
}

// ---------------- per-head L2 norm of q and k ----------------
__global__ __launch_bounds__(128) void qk_norm() {
    const int bt = blockIdx.x;
    const int hh = blockIdx.y;  // 0..15 q, 16..31 k
    const int off = (hh < HH) ? hh * DK : (HH * DK + (hh - HH) * DK);
    const float* src = g_y + (size_t)bt * CDIM + off;
    float u = src[threadIdx.x];
    float s = u * u;
#pragma unroll
    for (int o = 16; o; o >>= 1) s += __shfl_xor_sync(0xffffffffu, s, o);
    __shared__ float red[4];
    if ((threadIdx.x & 31) == 0) red[threadIdx.x >> 5] = s;
    __syncthreads();
    float tot = red[0] + red[1] + red[2] + red[3];
    float r = rsqrtf(tot + 1e-6f);
    float* dst = (hh < HH) ? g_qn : g_kn;
    dst[(size_t)bt * 2048 + (hh & 15) * DK + threadIdx.x] = u * r;
}

// ---------------- sequential delta-rule scan ----------------
__global__ __launch_bounds__(128) void scan_kernel(float* __restrict__ o) {
    const int bh = blockIdx.x;
    const int b = bh >> 4, h = bh & 15;
    const int jc = blockIdx.y;
    const int tid = threadIdx.x;
    const int jloc = tid >> 2;
    const int kg = tid & 3;

    __shared__ float ks[2][132], qs[2][132], vs[2][32], sc[2][2];
    float S[32];
#pragma unroll
    for (int i = 0; i < 32; i++) S[i] = 0.f;

    const int skew = (tid >> 5) * 33 + (tid & 31);

    const size_t qkbase = ((size_t)b * TT) * 2048 + h * DK;
    const size_t vbase = ((size_t)b * TT) * CDIM + 2 * HH * DK + h * DV + jc * 32;
    const size_t gbase = ((size_t)b * TT) * HH + h;
    const size_t obase = ((size_t)b * TT) * 2048 + h * DV + jc * 32 + jloc;

    float rk = g_kn[qkbase + tid];
    float rq = g_qn[qkbase + tid];
    float rv = (tid < 32) ? g_y[vbase + tid] : 0.f;
    float rb = g_beta[gbase], rd = g_decay[gbase];
    ks[0][skew] = rk;
    qs[0][skew] = rq;
    if (tid < 32) vs[0][tid] = rv;
    if (tid == 0) { sc[0][0] = rb; sc[0][1] = rd; }
    __syncthreads();

    for (int t = 0; t < TT; t++) {
        const int cur = t & 1;
        if (t + 1 < TT) {
            const size_t to = (size_t)(t + 1);
            rk = g_kn[qkbase + to * 2048 + tid];
            rq = g_qn[qkbase + to * 2048 + tid];
            if (tid < 32) rv = g_y[vbase + to * CDIM + tid];
            rb = g_beta[gbase + to * HH];
            rd = g_decay[gbase + to * HH];
        }
        const float bet = sc[cur][0];
        const float dec = sc[cur][1];
        const float vv = vs[cur][jloc];

        float kreg[32];
        float kv = 0.f;
#pragma unroll
        for (int i = 0; i < 32; i++) {
            kreg[i] = ks[cur][kg * 33 + i];
            S[i] *= dec;
            kv += kreg[i] * S[i];
        }
        kv += __shfl_xor_sync(0xffffffffu, kv, 1);
        kv += __shfl_xor_sync(0xffffffffu, kv, 2);
        const float delta = (vv - kv) * bet;

        float oacc = 0.f;
#pragma unroll
        for (int i = 0; i < 32; i++) {
            S[i] += kreg[i] * delta;
            oacc += qs[cur][kg * 33 + i] * S[i];
        }
        oacc += __shfl_xor_sync(0xffffffffu, oacc, 1);
        oacc += __shfl_xor_sync(0xffffffffu, oacc, 2);
        if (kg == 0) o[obase + (size_t)t * 2048] = oacc;

        if (t + 1 < TT) {
            const int nxt = cur ^ 1;
            ks[nxt][skew] = rk;
            qs[nxt][skew] = rq;
            if (tid < 32) vs[nxt][tid] = rv;
            if (tid == 0) { sc[nxt][0] = rb; sc[nxt][1] = rd; }
        }
        __syncthreads();
    }
}

// ---------------- gated RMSNorm per head ----------------
__global__ __launch_bounds__(128) void gated_norm(const float* __restrict__ norm_w) {
    const int g = blockIdx.x;  // bt*16 + h
    float u = g_o[(size_t)g * DV + threadIdx.x];
    float s = u * u;
#pragma unroll
    for (int o = 16; o; o >>= 1) s += __shfl_xor_sync(0xffffffffu, s, o);
    __shared__ float red[4];
    if ((threadIdx.x & 31) == 0) red[threadIdx.x >> 5] = s;
    __syncthreads();
    float tot = red[0] + red[1] + red[2] + red[3];
    float r = rsqrtf(tot * (1.f / DV) + 1e-6f);
    float zz = g_z[(size_t)g * DV + threadIdx.x];
    float sil = zz / (1.f + expf(-zz));
    g_on[(size_t)g * DV + threadIdx.x] = u * r * norm_w[threadIdx.x] * sil;
}

// ---------------- launch ----------------
extern "C" void kernel_launch(void* const* d_in, const int* in_sizes, int n_in,
                              void* d_out, int out_size) {
    const float* x = (const float*)d_in[0];
    const float* w_qkv = (const float*)d_in[1];
    const float* conv_w = (const float*)d_in[2];
    const float* w_z = (const float*)d_in[3];
    const float* w_b = (const float*)d_in[4];
    const float* w_a = (const float*)d_in[5];
    const float* dt_bias = (const float*)d_in[6];
    const float* A_log = (const float*)d_in[7];
    const float* norm_w = (const float*)d_in[8];
    const float* w_out = (const float*)d_in[9];
    float* out = (float*)d_out;

    float* mixed; cudaGetSymbolAddress((void**)&mixed, g_mixed);
    float* z;     cudaGetSymbolAddress((void**)&z, g_z);
    float* o;     cudaGetSymbolAddress((void**)&o, g_o);
    float* on;    cudaGetSymbolAddress((void**)&on, g_on);

    // 1. mixed = x @ w_qkv^T   [4096 x 6144]
    gemm_tf32<<<dim3(CDIM / 128, MTOK / 128), 256>>>(x, w_qkv, mixed, MTOK, CDIM, DM);
    // 2. gates
    proj_gates<<<MTOK, 256>>>(x, w_b, w_a, dt_bias, A_log);
    // 3. conv + silu
    conv_silu<<<dim3(CDIM / 256, MTOK), 256>>>(conv_w);
    // 4. q/k l2 norm
    qk_norm<<<dim3(MTOK, 2 * HH), 128>>>();
    // 5. z = x @ w_z^T  [4096 x 2048]
    gemm_tf32<<<dim3(2048 / 128, MTOK / 128), 256>>>(x, w_z, z, MTOK, 2048, DM);
    // 6. scan
    scan_kernel<<<dim3(BB * HH, 4), 128>>>(o);
    // 7. gated rmsnorm
    gated_norm<<<MTOK * HH, 128>>>(norm_w);
    // 8. out = on @ w_out^T  [4096 x 2048]
    gemm_tf32<<<dim3(2048 / 128, MTOK / 128), 256>>>(on, w_out, out, MTOK, 2048, DM);
}

// round 9
// speedup vs baseline: 2.0287x; 1.3892x over previous
#include <cuda_runtime.h>
#include <cuda_bf16.h>
#include <stdint.h>
#include <math.h>

// Problem constants
#define BB 2
#define TT 2048
#define DM 2048
#define HH 16
#define DK 128
#define DV 128
#define KW 4
#define CDIM 6144          // 2*H*DK + H*DV
#define MTOK 4096          // B*T

// ---------------- scratch (device globals; no allocation allowed) ----------------
__device__ float g_mixed[(size_t)MTOK * CDIM];
__device__ float g_y[(size_t)MTOK * CDIM];
__device__ float g_qn[(size_t)MTOK * 2048];
__device__ float g_kn[(size_t)MTOK * 2048];
__device__ float g_beta[(size_t)MTOK * HH];
__device__ float g_decay[(size_t)MTOK * HH];
__device__ float g_o[(size_t)MTOK * 2048];
__device__ float g_z[(size_t)MTOK * 2048];
__device__ float g_on[(size_t)MTOK * 2048];

// bf16 hi/lo pre-split operands
__device__ __nv_bfloat16 g_xh[(size_t)MTOK * DM];
__device__ __nv_bfloat16 g_xl[(size_t)MTOK * DM];
__device__ __nv_bfloat16 g_wqh[(size_t)CDIM * DM];
__device__ __nv_bfloat16 g_wql[(size_t)CDIM * DM];
__device__ __nv_bfloat16 g_wzh[(size_t)2048 * DM];
__device__ __nv_bfloat16 g_wzl[(size_t)2048 * DM];
__device__ __nv_bfloat16 g_woh[(size_t)2048 * 2048];
__device__ __nv_bfloat16 g_wol[(size_t)2048 * 2048];
__device__ __nv_bfloat16 g_onh[(size_t)MTOK * 2048];
__device__ __nv_bfloat16 g_onl[(size_t)MTOK * 2048];

// ---------------- helpers ----------------
__device__ __forceinline__ void cp16(unsigned int dst, const void* src) {
    asm volatile("cp.async.cg.shared.global [%0], [%1], 16;" ::"r"(dst), "l"(src));
}

__device__ __forceinline__ unsigned short bfbits(__nv_bfloat16 v) {
    return *reinterpret_cast<unsigned short*>(&v);
}

// ---------------- bf16 hi/lo split ----------------
__global__ __launch_bounds__(256) void split_bf(const float* __restrict__ s,
                                                __nv_bfloat16* __restrict__ h,
                                                __nv_bfloat16* __restrict__ l, int n4) {
    int i = blockIdx.x * 256 + threadIdx.x;
    if (i >= n4) return;
    float4 v = ((const float4*)s)[i];
    __nv_bfloat16 h0 = __float2bfloat16(v.x);
    __nv_bfloat16 h1 = __float2bfloat16(v.y);
    __nv_bfloat16 h2 = __float2bfloat16(v.z);
    __nv_bfloat16 h3 = __float2bfloat16(v.w);
    __nv_bfloat16 l0 = __float2bfloat16(v.x - __bfloat162float(h0));
    __nv_bfloat16 l1 = __float2bfloat16(v.y - __bfloat162float(h1));
    __nv_bfloat16 l2 = __float2bfloat16(v.z - __bfloat162float(h2));
    __nv_bfloat16 l3 = __float2bfloat16(v.w - __bfloat162float(h3));
    uint2 ho, lo;
    ho.x = ((unsigned int)bfbits(h1) << 16) | bfbits(h0);
    ho.y = ((unsigned int)bfbits(h3) << 16) | bfbits(h2);
    lo.x = ((unsigned int)bfbits(l1) << 16) | bfbits(l0);
    lo.y = ((unsigned int)bfbits(l3) << 16) | bfbits(l2);
    ((uint2*)h)[i] = ho;
    ((uint2*)l)[i] = lo;
}

// ---------------- 3xBF16 split tensor-core GEMM ----------------
// C[m,n] = sum_k A[m,k]*B[n,k]; A,B pre-split bf16 hi/lo.
// 128x128 tile, BK=32, 256 threads (8 warps, warp tile 32x64), cp.async double buf.
// mma.sync m16n8k16; 3 terms: al*bh + ah*bl + ah*bh.
#define BKPAD 40                               // bf16 row stride: 80B = 20 banks (conflict-free)
#define TILE_ELE (128 * BKPAD)                 // bf16 elements per tile
#define TILE_B (TILE_ELE * 2)                  // 10240 bytes
#define STAGE_ELE (4 * TILE_ELE)               // Ah, Al, Bh, Bl
#define STAGE_B (4 * TILE_B)                   // 40960 bytes
#define GEMM_SMEM_B (2 * STAGE_B)              // 81920 bytes

__device__ __forceinline__ void mma16(float* c, const unsigned int* a, const unsigned int* b) {
    asm volatile(
        "mma.sync.aligned.m16n8k16.row.col.f32.bf16.bf16.f32 "
        "{%0,%1,%2,%3}, {%4,%5,%6,%7}, {%8,%9}, {%0,%1,%2,%3};"
        : "+f"(c[0]), "+f"(c[1]), "+f"(c[2]), "+f"(c[3])
        : "r"(a[0]), "r"(a[1]), "r"(a[2]), "r"(a[3]), "r"(b[0]), "r"(b[1]));
}

// stage one 128x32 bf16 tile into padded smem rows (2 x 16B chunks per thread)
__device__ __forceinline__ void stage_tile(unsigned int dst, const __nv_bfloat16* src,
                                           int K, int tid) {
    const int row = tid >> 1;
    const int c0 = (tid & 1) * 2;
    cp16(dst + (unsigned int)(row * 80 + c0 * 16), src + (size_t)row * K + c0 * 8);
    cp16(dst + (unsigned int)(row * 80 + (c0 + 1) * 16), src + (size_t)row * K + (c0 + 1) * 8);
}

__global__ __launch_bounds__(256, 2) void gemm_bf16(const __nv_bfloat16* __restrict__ Ah,
                                                    const __nv_bfloat16* __restrict__ Al,
                                                    const __nv_bfloat16* __restrict__ Bh,
                                                    const __nv_bfloat16* __restrict__ Bl,
                                                    float* __restrict__ C,
                                                    int M, int N, int K) {
    extern __shared__ __align__(16) __nv_bfloat16 sm[];

    const int tid = threadIdx.x;
    const int bm = blockIdx.y * 128, bn = blockIdx.x * 128;
    const int warp = tid >> 5, lane = tid & 31;
    const int wm = (warp & 3) * 32;      // warp m offset (4 warps in m)
    const int wn = (warp >> 2) * 64;     // warp n offset (2 warps in n)
    const int g = lane >> 2, tg = lane & 3;

    const __nv_bfloat16* Abh = Ah + (size_t)bm * K;
    const __nv_bfloat16* Abl = Al + (size_t)bm * K;
    const __nv_bfloat16* Bbh = Bh + (size_t)bn * K;
    const __nv_bfloat16* Bbl = Bl + (size_t)bn * K;

    const unsigned int smb = (unsigned int)__cvta_generic_to_shared(sm);

    float acc[2][8][4];
#pragma unroll
    for (int mi = 0; mi < 2; mi++)
#pragma unroll
        for (int ni = 0; ni < 8; ni++)
#pragma unroll
            for (int r = 0; r < 4; r++) acc[mi][ni][r] = 0.f;

    // stage slab 0 into buffer 0
    stage_tile(smb + 0 * TILE_B, Abh, K, tid);
    stage_tile(smb + 1 * TILE_B, Abl, K, tid);
    stage_tile(smb + 2 * TILE_B, Bbh, K, tid);
    stage_tile(smb + 3 * TILE_B, Bbl, K, tid);
    asm volatile("cp.async.commit_group;");

    const int nk = K >> 5;
    for (int j = 0; j < nk; j++) {
        const int buf = j & 1;
        if (j + 1 < nk) {
            const unsigned int db = smb + (buf ^ 1) * STAGE_B;
            const int ko = (j + 1) * 32;
            stage_tile(db + 0 * TILE_B, Abh + ko, K, tid);
            stage_tile(db + 1 * TILE_B, Abl + ko, K, tid);
            stage_tile(db + 2 * TILE_B, Bbh + ko, K, tid);
            stage_tile(db + 3 * TILE_B, Bbl + ko, K, tid);
            asm volatile("cp.async.commit_group;");
            asm volatile("cp.async.wait_group 1;");
        } else {
            asm volatile("cp.async.wait_group 0;");
        }
        __syncthreads();

        const __nv_bfloat16* As_h = sm + buf * STAGE_ELE;
        const __nv_bfloat16* As_l = As_h + TILE_ELE;
        const __nv_bfloat16* Bs_h = As_h + 2 * TILE_ELE;
        const __nv_bfloat16* Bs_l = As_h + 3 * TILE_ELE;

#pragma unroll
        for (int kk = 0; kk < 32; kk += 16) {
            unsigned int ah[2][4], al[2][4];
#pragma unroll
            for (int mi = 0; mi < 2; mi++) {
                const int m = wm + mi * 16 + g;
                const int kc = kk + 2 * tg;
                ah[mi][0] = *(const unsigned int*)(As_h + m * BKPAD + kc);
                ah[mi][1] = *(const unsigned int*)(As_h + (m + 8) * BKPAD + kc);
                ah[mi][2] = *(const unsigned int*)(As_h + m * BKPAD + kc + 8);
                ah[mi][3] = *(const unsigned int*)(As_h + (m + 8) * BKPAD + kc + 8);
                al[mi][0] = *(const unsigned int*)(As_l + m * BKPAD + kc);
                al[mi][1] = *(const unsigned int*)(As_l + (m + 8) * BKPAD + kc);
                al[mi][2] = *(const unsigned int*)(As_l + m * BKPAD + kc + 8);
                al[mi][3] = *(const unsigned int*)(As_l + (m + 8) * BKPAD + kc + 8);
            }
#pragma unroll
            for (int ni = 0; ni < 8; ni++) {
                const int n = wn + ni * 8 + g;
                const int kc = kk + 2 * tg;
                unsigned int bh[2], bl[2];
                bh[0] = *(const unsigned int*)(Bs_h + n * BKPAD + kc);
                bh[1] = *(const unsigned int*)(Bs_h + n * BKPAD + kc + 8);
                bl[0] = *(const unsigned int*)(Bs_l + n * BKPAD + kc);
                bl[1] = *(const unsigned int*)(Bs_l + n * BKPAD + kc + 8);
#pragma unroll
                for (int mi = 0; mi < 2; mi++) {
                    mma16(acc[mi][ni], al[mi], bh);
                    mma16(acc[mi][ni], ah[mi], bl);
                    mma16(acc[mi][ni], ah[mi], bh);
                }
            }
        }
        __syncthreads();
    }

    // epilogue: c0,c1 at (row g, col 2tg), c2,c3 at (row g+8, col 2tg)
#pragma unroll
    for (int mi = 0; mi < 2; mi++) {
#pragma unroll
        for (int ni = 0; ni < 8; ni++) {
            const int r0 = bm + wm + mi * 16 + g;
            const int cc = bn + wn + ni * 8 + tg * 2;
            *(float2*)(C + (size_t)r0 * N + cc) =
                make_float2(acc[mi][ni][0], acc[mi][ni][1]);
            *(float2*)(C + (size_t)(r0 + 8) * N + cc) =
                make_float2(acc[mi][ni][2], acc[mi][ni][3]);
        }
    }
}

// ---------------- gates: beta = sigmoid(x.w_b), decay = exp(-exp(A_log)*softplus(x.w_a+dt_bias)) ----
__global__ __launch_bounds__(256) void proj_gates(const float* __restrict__ x,
                                                  const float* __restrict__ w_b,
                                                  const float* __restrict__ w_a,
                                                  const float* __restrict__ dt_bias,
                                                  const float* __restrict__ A_log) {
    const int m = blockIdx.x;
    __shared__ float xs[DM];
    for (int i = threadIdx.x; i < DM; i += 256) xs[i] = x[(size_t)m * DM + i];
    __syncthreads();
    const int warp = threadIdx.x >> 5, lane = threadIdx.x & 31;
    for (int d = warp; d < 32; d += 8) {
        const float* w = (d < HH) ? (w_b + (size_t)d * DM) : (w_a + (size_t)(d - HH) * DM);
        float s = 0.f;
        for (int i = lane; i < DM; i += 32) s += xs[i] * w[i];
#pragma unroll
        for (int off = 16; off; off >>= 1) s += __shfl_xor_sync(0xffffffffu, s, off);
        if (lane == 0) {
            if (d < HH) {
                g_beta[(size_t)m * HH + d] = 1.f / (1.f + expf(-s));
            } else {
                int h = d - HH;
                float sp = s + dt_bias[h];
                sp = (sp > 20.f) ? sp : log1pf(expf(sp));
                g_decay[(size_t)m * HH + h] = expf(-expf(A_log[h]) * sp);
            }
        }
    }
}

// ---------------- causal depthwise conv (KW=4) + SiLU ----------------
__global__ __launch_bounds__(256) void conv_silu(const float* __restrict__ conv_w) {
    const int c = blockIdx.x * 256 + threadIdx.x;
    const int bt = blockIdx.y;
    const int t = bt & (TT - 1);
    const float* base = g_mixed + (size_t)bt * CDIM + c;
    float4 w = *(const float4*)(conv_w + (size_t)c * KW);
    float acc = w.w * base[0];
    if (t >= 1) acc += w.z * base[-(ptrdiff_t)CDIM];
    if (t >= 2) acc += w.y * base[-(ptrdiff_t)(2 * CDIM)];
    if (t >= 3) acc += w.x * base[-(ptrdiff_t)(3 * CDIM)];
    float s = acc / (1.f + expf(-acc));
    g_y[(size_t)bt * CDIM + c] = s;
}

// ---------------- per-head L2 norm of q and k ----------------
__global__ __launch_bounds__(128) void qk_norm() {
    const int bt = blockIdx.x;
    const int hh = blockIdx.y;  // 0..15 q, 16..31 k
    const int off = (hh < HH) ? hh * DK : (HH * DK + (hh - HH) * DK);
    const float* src = g_y + (size_t)bt * CDIM + off;
    float u = src[threadIdx.x];
    float s = u * u;
#pragma unroll
    for (int o = 16; o; o >>= 1) s += __shfl_xor_sync(0xffffffffu, s, o);
    __shared__ float red[4];
    if ((threadIdx.x & 31) == 0) red[threadIdx.x >> 5] = s;
    __syncthreads();
    float tot = red[0] + red[1] + red[2] + red[3];
    float r = rsqrtf(tot + 1e-6f);
    float* dst = (hh < HH) ? g_qn : g_kn;
    dst[(size_t)bt * 2048 + (hh & 15) * DK + threadIdx.x] = u * r;
}

// ---------------- sequential delta-rule scan ----------------
__global__ __launch_bounds__(128) void scan_kernel(float* __restrict__ o) {
    const int bh = blockIdx.x;
    const int b = bh >> 4, h = bh & 15;
    const int jc = blockIdx.y;
    const int tid = threadIdx.x;
    const int jloc = tid >> 2;
    const int kg = tid & 3;

    __shared__ float ks[2][132], qs[2][132], vs[2][32], sc[2][2];
    float S[32];
#pragma unroll
    for (int i = 0; i < 32; i++) S[i] = 0.f;

    const int skew = (tid >> 5) * 33 + (tid & 31);

    const size_t qkbase = ((size_t)b * TT) * 2048 + h * DK;
    const size_t vbase = ((size_t)b * TT) * CDIM + 2 * HH * DK + h * DV + jc * 32;
    const size_t gbase = ((size_t)b * TT) * HH + h;
    const size_t obase = ((size_t)b * TT) * 2048 + h * DV + jc * 32 + jloc;

    float rk = g_kn[qkbase + tid];
    float rq = g_qn[qkbase + tid];
    float rv = (tid < 32) ? g_y[vbase + tid] : 0.f;
    float rb = g_beta[gbase], rd = g_decay[gbase];
    ks[0][skew] = rk;
    qs[0][skew] = rq;
    if (tid < 32) vs[0][tid] = rv;
    if (tid == 0) { sc[0][0] = rb; sc[0][1] = rd; }
    __syncthreads();

    for (int t = 0; t < TT; t++) {
        const int cur = t & 1;
        if (t + 1 < TT) {
            const size_t to = (size_t)(t + 1);
            rk = g_kn[qkbase + to * 2048 + tid];
            rq = g_qn[qkbase + to * 2048 + tid];
            if (tid < 32) rv = g_y[vbase + to * CDIM + tid];
            rb = g_beta[gbase + to * HH];
            rd = g_decay[gbase + to * HH];
        }
        const float bet = sc[cur][0];
        const float dec = sc[cur][1];
        const float vv = vs[cur][jloc];

        float kreg[32];
        float kv = 0.f;
#pragma unroll
        for (int i = 0; i < 32; i++) {
            kreg[i] = ks[cur][kg * 33 + i];
            S[i] *= dec;
            kv += kreg[i] * S[i];
        }
        kv += __shfl_xor_sync(0xffffffffu, kv, 1);
        kv += __shfl_xor_sync(0xffffffffu, kv, 2);
        const float delta = (vv - kv) * bet;

        float oacc = 0.f;
#pragma unroll
        for (int i = 0; i < 32; i++) {
            S[i] += kreg[i] * delta;
            oacc += qs[cur][kg * 33 + i] * S[i];
        }
        oacc += __shfl_xor_sync(0xffffffffu, oacc, 1);
        oacc += __shfl_xor_sync(0xffffffffu, oacc, 2);
        if (kg == 0) o[obase + (size_t)t * 2048] = oacc;

        if (t + 1 < TT) {
            const int nxt = cur ^ 1;
            ks[nxt][skew] = rk;
            qs[nxt][skew] = rq;
            if (tid < 32) vs[nxt][tid] = rv;
            if (tid == 0) { sc[nxt][0] = rb; sc[nxt][1] = rd; }
        }
        __syncthreads();
    }
}

// ---------------- gated RMSNorm per head ----------------
__global__ __launch_bounds__(128) void gated_norm(const float* __restrict__ norm_w) {
    const int g = blockIdx.x;  // bt*16 + h
    float u = g_o[(size_t)g * DV + threadIdx.x];
    float s = u * u;
#pragma unroll
    for (int o = 16; o; o >>= 1) s += __shfl_xor_sync(0xffffffffu, s, o);
    __shared__ float red[4];
    if ((threadIdx.x & 31) == 0) red[threadIdx.x >> 5] = s;
    __syncthreads();
    float tot = red[0] + red[1] + red[2] + red[3];
    float r = rsqrtf(tot * (1.f / DV) + 1e-6f);
    float zz = g_z[(size_t)g * DV + threadIdx.x];
    float sil = zz / (1.f + expf(-zz));
    g_on[(size_t)g * DV + threadIdx.x] = u * r * norm_w[threadIdx.x] * sil;
}

// ---------------- launch ----------------
extern "C" void kernel_launch(void* const* d_in, const int* in_sizes, int n_in,
                              void* d_out, int out_size) {
    const float* x = (const float*)d_in[0];
    const float* w_qkv = (const float*)d_in[1];
    const float* conv_w = (const float*)d_in[2];
    const float* w_z = (const float*)d_in[3];
    const float* w_b = (const float*)d_in[4];
    const float* w_a = (const float*)d_in[5];
    const float* dt_bias = (const float*)d_in[6];
    const float* A_log = (const float*)d_in[7];
    const float* norm_w = (const float*)d_in[8];
    const float* w_out = (const float*)d_in[9];
    float* out = (float*)d_out;

    float *mixed, *z, *o, *on;
    __nv_bfloat16 *xh, *xl, *wqh, *wql, *wzh, *wzl, *woh, *wol, *onh, *onl;
    cudaGetSymbolAddress((void**)&mixed, g_mixed);
    cudaGetSymbolAddress((void**)&z, g_z);
    cudaGetSymbolAddress((void**)&o, g_o);
    cudaGetSymbolAddress((void**)&on, g_on);
    cudaGetSymbolAddress((void**)&xh, g_xh);
    cudaGetSymbolAddress((void**)&xl, g_xl);
    cudaGetSymbolAddress((void**)&wqh, g_wqh);
    cudaGetSymbolAddress((void**)&wql, g_wql);
    cudaGetSymbolAddress((void**)&wzh, g_wzh);
    cudaGetSymbolAddress((void**)&wzl, g_wzl);
    cudaGetSymbolAddress((void**)&woh, g_woh);
    cudaGetSymbolAddress((void**)&wol, g_wol);
    cudaGetSymbolAddress((void**)&onh, g_onh);
    cudaGetSymbolAddress((void**)&onl, g_onl);

    cudaFuncSetAttribute(gemm_bf16, cudaFuncAttributeMaxDynamicSharedMemorySize, GEMM_SMEM_B);

    // bf16 hi/lo pre-splits
    split_bf<<<(MTOK * DM / 4 + 255) / 256, 256>>>(x, xh, xl, MTOK * DM / 4);
    split_bf<<<(CDIM * DM / 4 + 255) / 256, 256>>>(w_qkv, wqh, wql, CDIM * DM / 4);
    split_bf<<<(2048 * DM / 4 + 255) / 256, 256>>>(w_z, wzh, wzl, 2048 * DM / 4);
    split_bf<<<(2048 * 2048 / 4 + 255) / 256, 256>>>(w_out, woh, wol, 2048 * 2048 / 4);

    // 1. mixed = x @ w_qkv^T   [4096 x 6144]
    gemm_bf16<<<dim3(CDIM / 128, MTOK / 128), 256, GEMM_SMEM_B>>>(xh, xl, wqh, wql, mixed,
                                                                  MTOK, CDIM, DM);
    // 2. gates
    proj_gates<<<MTOK, 256>>>(x, w_b, w_a, dt_bias, A_log);
    // 3. conv + silu
    conv_silu<<<dim3(CDIM / 256, MTOK), 256>>>(conv_w);
    // 4. q/k l2 norm
    qk_norm<<<dim3(MTOK, 2 * HH), 128>>>();
    // 5. z = x @ w_z^T  [4096 x 2048]
    gemm_bf16<<<dim3(2048 / 128, MTOK / 128), 256, GEMM_SMEM_B>>>(xh, xl, wzh, wzl, z,
                                                                  MTOK, 2048, DM);
    // 6. scan
    scan_kernel<<<dim3(BB * HH, 4), 128>>>(o);
    // 7. gated rmsnorm
    gated_norm<<<MTOK * HH, 128>>>(norm_w);
    // 8. split on, then out = on @ w_out^T  [4096 x 2048]
    split_bf<<<(MTOK * 2048 / 4 + 255) / 256, 256>>>(on, onh, onl, MTOK * 2048 / 4);
    gemm_bf16<<<dim3(2048 / 128, MTOK / 128), 256, GEMM_SMEM_B>>>(onh, onl, woh, wol, out,
                                                                  MTOK, 2048, DM);
}

// round 10
// speedup vs baseline: 2.1741x; 1.0717x over previous
#include <cuda_runtime.h>
#include <cuda_bf16.h>
#include <stdint.h>
#include <math.h>

// Problem constants
#define BB 2
#define TT 2048
#define DM 2048
#define HH 16
#define DK 128
#define DV 128
#define KW 4
#define CDIM 6144          // 2*H*DK + H*DV
#define MTOK 4096          // B*T

// ---------------- scratch (device globals; no allocation allowed) ----------------
__device__ float g_mixed[(size_t)MTOK * CDIM];
__device__ float g_y[(size_t)MTOK * CDIM];
__device__ float g_qn[(size_t)MTOK * 2048];
__device__ float g_kn[(size_t)MTOK * 2048];
__device__ float g_beta[(size_t)MTOK * HH];
__device__ float g_decay[(size_t)MTOK * HH];
__device__ float g_o[(size_t)MTOK * 2048];
__device__ float g_z[(size_t)MTOK * 2048];
__device__ float g_on[(size_t)MTOK * 2048];

// bf16 hi/lo pre-split operands
__device__ __nv_bfloat16 g_xh[(size_t)MTOK * DM];
__device__ __nv_bfloat16 g_xl[(size_t)MTOK * DM];
__device__ __nv_bfloat16 g_wqh[(size_t)CDIM * DM];
__device__ __nv_bfloat16 g_wql[(size_t)CDIM * DM];
__device__ __nv_bfloat16 g_wzh[(size_t)2048 * DM];
__device__ __nv_bfloat16 g_wzl[(size_t)2048 * DM];
__device__ __nv_bfloat16 g_woh[(size_t)2048 * 2048];
__device__ __nv_bfloat16 g_wol[(size_t)2048 * 2048];
__device__ __nv_bfloat16 g_onh[(size_t)MTOK * 2048];
__device__ __nv_bfloat16 g_onl[(size_t)MTOK * 2048];

// ---------------- helpers ----------------
__device__ __forceinline__ void cp16(unsigned int dst, const void* src) {
    asm volatile("cp.async.cg.shared.global [%0], [%1], 16;" ::"r"(dst), "l"(src));
}

__device__ __forceinline__ unsigned short bfbits(__nv_bfloat16 v) {
    return *reinterpret_cast<unsigned short*>(&v);
}

__device__ __forceinline__ void ldsm4(unsigned int* r, unsigned int addr) {
    asm volatile("ldmatrix.sync.aligned.m8n8.x4.shared.b16 {%0,%1,%2,%3}, [%4];"
                 : "=r"(r[0]), "=r"(r[1]), "=r"(r[2]), "=r"(r[3])
                 : "r"(addr));
}

// ---------------- bf16 hi/lo split ----------------
__global__ __launch_bounds__(256) void split_bf(const float* __restrict__ s,
                                                __nv_bfloat16* __restrict__ h,
                                                __nv_bfloat16* __restrict__ l, int n4) {
    int i = blockIdx.x * 256 + threadIdx.x;
    if (i >= n4) return;
    float4 v = ((const float4*)s)[i];
    __nv_bfloat16 h0 = __float2bfloat16(v.x);
    __nv_bfloat16 h1 = __float2bfloat16(v.y);
    __nv_bfloat16 h2 = __float2bfloat16(v.z);
    __nv_bfloat16 h3 = __float2bfloat16(v.w);
    __nv_bfloat16 l0 = __float2bfloat16(v.x - __bfloat162float(h0));
    __nv_bfloat16 l1 = __float2bfloat16(v.y - __bfloat162float(h1));
    __nv_bfloat16 l2 = __float2bfloat16(v.z - __bfloat162float(h2));
    __nv_bfloat16 l3 = __float2bfloat16(v.w - __bfloat162float(h3));
    uint2 ho, lo;
    ho.x = ((unsigned int)bfbits(h1) << 16) | bfbits(h0);
    ho.y = ((unsigned int)bfbits(h3) << 16) | bfbits(h2);
    lo.x = ((unsigned int)bfbits(l1) << 16) | bfbits(l0);
    lo.y = ((unsigned int)bfbits(l3) << 16) | bfbits(l2);
    ((uint2*)h)[i] = ho;
    ((uint2*)l)[i] = lo;
}

// ---------------- 3xBF16 split tensor-core GEMM (ldmatrix inner loop) ----------
// C[m,n] = sum_k A[m,k]*B[n,k]; A,B pre-split bf16 hi/lo.
// 128x128 tile, BK=32, 256 threads (8 warps, warp tile 32x64), cp.async double buf.
#define BKPAD 40                               // bf16 row stride: 80B = 20 banks
#define ROWB 80                                // bytes per smem row
#define TILE_ELE (128 * BKPAD)
#define TILE_B (TILE_ELE * 2)                  // 10240 bytes
#define STAGE_ELE (4 * TILE_ELE)
#define STAGE_B (4 * TILE_B)                   // 40960 bytes
#define GEMM_SMEM_B (2 * STAGE_B)              // 81920 bytes

__device__ __forceinline__ void mma16(float* c, const unsigned int* a,
                                      unsigned int b0, unsigned int b1) {
    asm volatile(
        "mma.sync.aligned.m16n8k16.row.col.f32.bf16.bf16.f32 "
        "{%0,%1,%2,%3}, {%4,%5,%6,%7}, {%8,%9}, {%0,%1,%2,%3};"
        : "+f"(c[0]), "+f"(c[1]), "+f"(c[2]), "+f"(c[3])
        : "r"(a[0]), "r"(a[1]), "r"(a[2]), "r"(a[3]), "r"(b0), "r"(b1));
}

// stage one 128x32 bf16 tile into padded smem rows (2 x 16B chunks per thread)
__device__ __forceinline__ void stage_tile(unsigned int dst, const __nv_bfloat16* src,
                                           int K, int tid) {
    const int row = tid >> 1;
    const int c0 = (tid & 1) * 2;
    cp16(dst + (unsigned int)(row * ROWB + c0 * 16), src + (size_t)row * K + c0 * 8);
    cp16(dst + (unsigned int)(row * ROWB + (c0 + 1) * 16), src + (size_t)row * K + (c0 + 1) * 8);
}

// core GEMM body; called with resolved B/C pointers
__device__ __forceinline__ void gemm_body(const __nv_bfloat16* Abh,
                                          const __nv_bfloat16* Abl,
                                          const __nv_bfloat16* Bbh,
                                          const __nv_bfloat16* Bbl,
                                          float* __restrict__ Crow0,
                                          int N, int K) {
    extern __shared__ __align__(16) __nv_bfloat16 sm[];
    const int tid = threadIdx.x;
    const int warp = tid >> 5, lane = tid & 31;
    const int wm = (warp & 3) * 32;      // warp m offset
    const int wn = (warp >> 2) * 64;     // warp n offset
    const int g = lane >> 2, tg = lane & 3;

    const unsigned int smb = (unsigned int)__cvta_generic_to_shared(sm);

    // ldmatrix per-lane byte offsets within a tile
    const unsigned int aLane =
        (unsigned int)((wm + (lane & 7) + ((lane & 8) ? 8 : 0)) * ROWB +
                       ((lane & 16) ? 16 : 0));
    const unsigned int bLane =
        (unsigned int)((wn + (lane & 7) + ((lane & 16) ? 8 : 0)) * ROWB +
                       ((lane & 8) ? 16 : 0));

    float acc[2][8][4];
#pragma unroll
    for (int mi = 0; mi < 2; mi++)
#pragma unroll
        for (int ni = 0; ni < 8; ni++)
#pragma unroll
            for (int r = 0; r < 4; r++) acc[mi][ni][r] = 0.f;

    stage_tile(smb + 0 * TILE_B, Abh, K, tid);
    stage_tile(smb + 1 * TILE_B, Abl, K, tid);
    stage_tile(smb + 2 * TILE_B, Bbh, K, tid);
    stage_tile(smb + 3 * TILE_B, Bbl, K, tid);
    asm volatile("cp.async.commit_group;");

    const int nk = K >> 5;
    for (int j = 0; j < nk; j++) {
        const int buf = j & 1;
        if (j + 1 < nk) {
            const unsigned int db = smb + (buf ^ 1) * STAGE_B;
            const int ko = (j + 1) * 32;
            stage_tile(db + 0 * TILE_B, Abh + ko, K, tid);
            stage_tile(db + 1 * TILE_B, Abl + ko, K, tid);
            stage_tile(db + 2 * TILE_B, Bbh + ko, K, tid);
            stage_tile(db + 3 * TILE_B, Bbl + ko, K, tid);
            asm volatile("cp.async.commit_group;");
            asm volatile("cp.async.wait_group 1;");
        } else {
            asm volatile("cp.async.wait_group 0;");
        }
        __syncthreads();

        const unsigned int tAh = smb + buf * STAGE_B;
        const unsigned int tAl = tAh + TILE_B;
        const unsigned int tBh = tAh + 2 * TILE_B;
        const unsigned int tBl = tAh + 3 * TILE_B;

#pragma unroll
        for (int kk = 0; kk < 32; kk += 16) {
            const unsigned int kb = (unsigned int)(kk * 2);
            unsigned int ah[2][4], al[2][4];
            ldsm4(ah[0], tAh + kb + aLane);
            ldsm4(ah[1], tAh + kb + aLane + 16 * ROWB);
            ldsm4(al[0], tAl + kb + aLane);
            ldsm4(al[1], tAl + kb + aLane + 16 * ROWB);
#pragma unroll
            for (int p = 0; p < 4; p++) {  // ni pair p -> ni = 2p, 2p+1
                const unsigned int po = kb + (unsigned int)(p * 16 * ROWB) + bLane;
                unsigned int bh[4], bl[4];
                ldsm4(bh, tBh + po);
                ldsm4(bl, tBl + po);
#pragma unroll
                for (int mi = 0; mi < 2; mi++) {
                    mma16(acc[mi][2 * p], al[mi], bh[0], bh[1]);
                    mma16(acc[mi][2 * p], ah[mi], bl[0], bl[1]);
                    mma16(acc[mi][2 * p], ah[mi], bh[0], bh[1]);
                    mma16(acc[mi][2 * p + 1], al[mi], bh[2], bh[3]);
                    mma16(acc[mi][2 * p + 1], ah[mi], bl[2], bl[3]);
                    mma16(acc[mi][2 * p + 1], ah[mi], bh[2], bh[3]);
                }
            }
        }
        __syncthreads();
    }

#pragma unroll
    for (int mi = 0; mi < 2; mi++) {
#pragma unroll
        for (int ni = 0; ni < 8; ni++) {
            const int r0 = wm + mi * 16 + g;
            const int cc = wn + ni * 8 + tg * 2;
            *(float2*)(Crow0 + (size_t)r0 * N + cc) =
                make_float2(acc[mi][ni][0], acc[mi][ni][1]);
            *(float2*)(Crow0 + (size_t)(r0 + 8) * N + cc) =
                make_float2(acc[mi][ni][2], acc[mi][ni][3]);
        }
    }
}

__global__ __launch_bounds__(256, 2) void gemm_bf16(const __nv_bfloat16* __restrict__ Ah,
                                                    const __nv_bfloat16* __restrict__ Al,
                                                    const __nv_bfloat16* __restrict__ Bh,
                                                    const __nv_bfloat16* __restrict__ Bl,
                                                    float* __restrict__ C,
                                                    int M, int N, int K) {
    const int bm = blockIdx.y * 128, bn = blockIdx.x * 128;
    gemm_body(Ah + (size_t)bm * K, Al + (size_t)bm * K,
              Bh + (size_t)bn * K, Bl + (size_t)bn * K,
              C + (size_t)bm * N + bn, N, K);
}

// fused qkv + z projection: blocks with bn < CDIM do mixed, rest do z
__global__ __launch_bounds__(256, 2) void gemm_bf16_dual(
    const __nv_bfloat16* __restrict__ Ah, const __nv_bfloat16* __restrict__ Al,
    const __nv_bfloat16* __restrict__ B1h, const __nv_bfloat16* __restrict__ B1l,
    float* __restrict__ C1, int N1,
    const __nv_bfloat16* __restrict__ B2h, const __nv_bfloat16* __restrict__ B2l,
    float* __restrict__ C2, int N2, int K) {
    const int bm = blockIdx.y * 128;
    int bn = blockIdx.x * 128;
    const __nv_bfloat16 *Bh, *Bl;
    float* C;
    int N;
    if (bn < N1) {
        Bh = B1h; Bl = B1l; C = C1; N = N1;
    } else {
        bn -= N1;
        Bh = B2h; Bl = B2l; C = C2; N = N2;
    }
    gemm_body(Ah + (size_t)bm * K, Al + (size_t)bm * K,
              Bh + (size_t)bn * K, Bl + (size_t)bn * K,
              C + (size_t)bm * N + bn, N, K);
}

// ---------------- gates ----------------
__global__ __launch_bounds__(256) void proj_gates(const float* __restrict__ x,
                                                  const float* __restrict__ w_b,
                                                  const float* __restrict__ w_a,
                                                  const float* __restrict__ dt_bias,
                                                  const float* __restrict__ A_log) {
    const int m = blockIdx.x;
    __shared__ float xs[DM];
    for (int i = threadIdx.x; i < DM; i += 256) xs[i] = x[(size_t)m * DM + i];
    __syncthreads();
    const int warp = threadIdx.x >> 5, lane = threadIdx.x & 31;
    for (int d = warp; d < 32; d += 8) {
        const float* w = (d < HH) ? (w_b + (size_t)d * DM) : (w_a + (size_t)(d - HH) * DM);
        float s = 0.f;
        for (int i = lane; i < DM; i += 32) s += xs[i] * w[i];
#pragma unroll
        for (int off = 16; off; off >>= 1) s += __shfl_xor_sync(0xffffffffu, s, off);
        if (lane == 0) {
            if (d < HH) {
                g_beta[(size_t)m * HH + d] = 1.f / (1.f + expf(-s));
            } else {
                int h = d - HH;
                float sp = s + dt_bias[h];
                sp = (sp > 20.f) ? sp : log1pf(expf(sp));
                g_decay[(size_t)m * HH + h] = expf(-expf(A_log[h]) * sp);
            }
        }
    }
}

// ---------------- causal depthwise conv (KW=4) + SiLU ----------------
__global__ __launch_bounds__(256) void conv_silu(const float* __restrict__ conv_w) {
    const int c = blockIdx.x * 256 + threadIdx.x;
    const int bt = blockIdx.y;
    const int t = bt & (TT - 1);
    const float* base = g_mixed + (size_t)bt * CDIM + c;
    float4 w = *(const float4*)(conv_w + (size_t)c * KW);
    float acc = w.w * base[0];
    if (t >= 1) acc += w.z * base[-(ptrdiff_t)CDIM];
    if (t >= 2) acc += w.y * base[-(ptrdiff_t)(2 * CDIM)];
    if (t >= 3) acc += w.x * base[-(ptrdiff_t)(3 * CDIM)];
    float s = acc / (1.f + expf(-acc));
    g_y[(size_t)bt * CDIM + c] = s;
}

// ---------------- per-head L2 norm of q and k ----------------
__global__ __launch_bounds__(128) void qk_norm() {
    const int bt = blockIdx.x;
    const int hh = blockIdx.y;  // 0..15 q, 16..31 k
    const int off = (hh < HH) ? hh * DK : (HH * DK + (hh - HH) * DK);
    const float* src = g_y + (size_t)bt * CDIM + off;
    float u = src[threadIdx.x];
    float s = u * u;
#pragma unroll
    for (int o = 16; o; o >>= 1) s += __shfl_xor_sync(0xffffffffu, s, o);
    __shared__ float red[4];
    if ((threadIdx.x & 31) == 0) red[threadIdx.x >> 5] = s;
    __syncthreads();
    float tot = red[0] + red[1] + red[2] + red[3];
    float r = rsqrtf(tot + 1e-6f);
    float* dst = (hh < HH) ? g_qn : g_kn;
    dst[(size_t)bt * 2048 + (hh & 15) * DK + threadIdx.x] = u * r;
}

// ---------------- sequential delta-rule scan ----------------
__global__ __launch_bounds__(128) void scan_kernel(float* __restrict__ o) {
    const int bh = blockIdx.x;
    const int b = bh >> 4, h = bh & 15;
    const int jc = blockIdx.y;
    const int tid = threadIdx.x;
    const int jloc = tid >> 2;
    const int kg = tid & 3;

    __shared__ float ks[2][132], qs[2][132], vs[2][32], sc[2][2];
    float S[32];
#pragma unroll
    for (int i = 0; i < 32; i++) S[i] = 0.f;

    const int skew = (tid >> 5) * 33 + (tid & 31);

    const size_t qkbase = ((size_t)b * TT) * 2048 + h * DK;
    const size_t vbase = ((size_t)b * TT) * CDIM + 2 * HH * DK + h * DV + jc * 32;
    const size_t gbase = ((size_t)b * TT) * HH + h;
    const size_t obase = ((size_t)b * TT) * 2048 + h * DV + jc * 32 + jloc;

    float rk = g_kn[qkbase + tid];
    float rq = g_qn[qkbase + tid];
    float rv = (tid < 32) ? g_y[vbase + tid] : 0.f;
    float rb = g_beta[gbase], rd = g_decay[gbase];
    ks[0][skew] = rk;
    qs[0][skew] = rq;
    if (tid < 32) vs[0][tid] = rv;
    if (tid == 0) { sc[0][0] = rb; sc[0][1] = rd; }
    __syncthreads();

    for (int t = 0; t < TT; t++) {
        const int cur = t & 1;
        if (t + 1 < TT) {
            const size_t to = (size_t)(t + 1);
            rk = g_kn[qkbase + to * 2048 + tid];
            rq = g_qn[qkbase + to * 2048 + tid];
            if (tid < 32) rv = g_y[vbase + to * CDIM + tid];
            rb = g_beta[gbase + to * HH];
            rd = g_decay[gbase + to * HH];
        }
        const float bet = sc[cur][0];
        const float dec = sc[cur][1];
        const float vv = vs[cur][jloc];

        float kreg[32];
        float kv = 0.f;
#pragma unroll
        for (int i = 0; i < 32; i++) {
            kreg[i] = ks[cur][kg * 33 + i];
            S[i] *= dec;
            kv += kreg[i] * S[i];
        }
        kv += __shfl_xor_sync(0xffffffffu, kv, 1);
        kv += __shfl_xor_sync(0xffffffffu, kv, 2);
        const float delta = (vv - kv) * bet;

        float oacc = 0.f;
#pragma unroll
        for (int i = 0; i < 32; i++) {
            S[i] += kreg[i] * delta;
            oacc += qs[cur][kg * 33 + i] * S[i];
        }
        oacc += __shfl_xor_sync(0xffffffffu, oacc, 1);
        oacc += __shfl_xor_sync(0xffffffffu, oacc, 2);
        if (kg == 0) o[obase + (size_t)t * 2048] = oacc;

        if (t + 1 < TT) {
            const int nxt = cur ^ 1;
            ks[nxt][skew] = rk;
            qs[nxt][skew] = rq;
            if (tid < 32) vs[nxt][tid] = rv;
            if (tid == 0) { sc[nxt][0] = rb; sc[nxt][1] = rd; }
        }
        __syncthreads();
    }
}

// ---------------- gated RMSNorm per head ----------------
__global__ __launch_bounds__(128) void gated_norm(const float* __restrict__ norm_w) {
    const int g = blockIdx.x;  // bt*16 + h
    float u = g_o[(size_t)g * DV + threadIdx.x];
    float s = u * u;
#pragma unroll
    for (int o = 16; o; o >>= 1) s += __shfl_xor_sync(0xffffffffu, s, o);
    __shared__ float red[4];
    if ((threadIdx.x & 31) == 0) red[threadIdx.x >> 5] = s;
    __syncthreads();
    float tot = red[0] + red[1] + red[2] + red[3];
    float r = rsqrtf(tot * (1.f / DV) + 1e-6f);
    float zz = g_z[(size_t)g * DV + threadIdx.x];
    float sil = zz / (1.f + expf(-zz));
    g_on[(size_t)g * DV + threadIdx.x] = u * r * norm_w[threadIdx.x] * sil;
}

// ---------------- launch ----------------
extern "C" void kernel_launch(void* const* d_in, const int* in_sizes, int n_in,
                              void* d_out, int out_size) {
    const float* x = (const float*)d_in[0];
    const float* w_qkv = (const float*)d_in[1];
    const float* conv_w = (const float*)d_in[2];
    const float* w_z = (const float*)d_in[3];
    const float* w_b = (const float*)d_in[4];
    const float* w_a = (const float*)d_in[5];
    const float* dt_bias = (const float*)d_in[6];
    const float* A_log = (const float*)d_in[7];
    const float* norm_w = (const float*)d_in[8];
    const float* w_out = (const float*)d_in[9];
    float* out = (float*)d_out;

    float *mixed, *z, *o, *on;
    __nv_bfloat16 *xh, *xl, *wqh, *wql, *wzh, *wzl, *woh, *wol, *onh, *onl;
    cudaGetSymbolAddress((void**)&mixed, g_mixed);
    cudaGetSymbolAddress((void**)&z, g_z);
    cudaGetSymbolAddress((void**)&o, g_o);
    cudaGetSymbolAddress((void**)&on, g_on);
    cudaGetSymbolAddress((void**)&xh, g_xh);
    cudaGetSymbolAddress((void**)&xl, g_xl);
    cudaGetSymbolAddress((void**)&wqh, g_wqh);
    cudaGetSymbolAddress((void**)&wql, g_wql);
    cudaGetSymbolAddress((void**)&wzh, g_wzh);
    cudaGetSymbolAddress((void**)&wzl, g_wzl);
    cudaGetSymbolAddress((void**)&woh, g_woh);
    cudaGetSymbolAddress((void**)&wol, g_wol);
    cudaGetSymbolAddress((void**)&onh, g_onh);
    cudaGetSymbolAddress((void**)&onl, g_onl);

    cudaFuncSetAttribute(gemm_bf16, cudaFuncAttributeMaxDynamicSharedMemorySize, GEMM_SMEM_B);
    cudaFuncSetAttribute(gemm_bf16_dual, cudaFuncAttributeMaxDynamicSharedMemorySize,
                         GEMM_SMEM_B);

    // bf16 hi/lo pre-splits
    split_bf<<<(MTOK * DM / 4 + 255) / 256, 256>>>(x, xh, xl, MTOK * DM / 4);
    split_bf<<<(CDIM * DM / 4 + 255) / 256, 256>>>(w_qkv, wqh, wql, CDIM * DM / 4);
    split_bf<<<(2048 * DM / 4 + 255) / 256, 256>>>(w_z, wzh, wzl, 2048 * DM / 4);
    split_bf<<<(2048 * 2048 / 4 + 255) / 256, 256>>>(w_out, woh, wol, 2048 * 2048 / 4);

    // 1+5 fused: mixed = x@w_qkv^T and z = x@w_z^T
    gemm_bf16_dual<<<dim3((CDIM + 2048) / 128, MTOK / 128), 256, GEMM_SMEM_B>>>(
        xh, xl, wqh, wql, mixed, CDIM, wzh, wzl, z, 2048, DM);
    // 2. gates
    proj_gates<<<MTOK, 256>>>(x, w_b, w_a, dt_bias, A_log);
    // 3. conv + silu
    conv_silu<<<dim3(CDIM / 256, MTOK), 256>>>(conv_w);
    // 4. q/k l2 norm
    qk_norm<<<dim3(MTOK, 2 * HH), 128>>>();
    // 6. scan
    scan_kernel<<<dim3(BB * HH, 4), 128>>>(o);
    // 7. gated rmsnorm
    gated_norm<<<MTOK * HH, 128>>>(norm_w);
    // 8. split on, then out = on @ w_out^T
    split_bf<<<(MTOK * 2048 / 4 + 255) / 256, 256>>>(on, onh, onl, MTOK * 2048 / 4);
    gemm_bf16<<<dim3(2048 / 128, MTOK / 128), 256, GEMM_SMEM_B>>>(onh, onl, woh, wol, out,
                                                                  MTOK, 2048, DM);
}